// round 16
// baseline (speedup 1.0000x reference)
#include <cuda_runtime.h>
#include <cuda_fp16.h>
#include <cstdint>

// ---------------- problem constants ----------------
#define IN_DIM   128
#define HIDDEN   256
#define OUT_DIM  64
#define N_NODES_MAX 100000

// Does this device-compile pass support tcgen05? (arch-specific or family target)
#if defined(__CUDA_ARCH__)
#  if defined(__CUDA_ARCH_FEAT_SM103_ALL) || defined(__CUDA_ARCH_FEAT_SM100_ALL) || \
      (defined(__CUDA_ARCH_FAMILY_SPECIFIC__) && (__CUDA_ARCH_FAMILY_SPECIFIC__ >= 1000))
#    define HAS_TCGEN05 1
#  else
#    define HAS_TCGEN05 0
#  endif
#else
#  define HAS_TCGEN05 0
#endif

// ---------------- device scratch (no allocs allowed) ----------------
__device__ __half        g_xh[(size_t)N_NODES_MAX * IN_DIM];   // 25.6 MB fp16 node features
__device__ unsigned char g_w1t[HIDDEN * (2 * IN_DIM) * 2];     // SW128 image for tcgen05 path
__device__ unsigned char g_w2t[OUT_DIM * HIDDEN * 2];          // SW128 image for tcgen05 path
__device__ __half        g_w1h[HIDDEN * (2 * IN_DIM)];         // [n][k] linear fp16 (HMMA path)
__device__ __half        g_w2h[OUT_DIM * HIDDEN];              // [n][k] linear fp16 (HMMA path)

// ---------------- common helpers ----------------
__device__ __forceinline__ uint32_t smem_u32(const void* p) {
    uint32_t a;
    asm("{ .reg .u64 t; cvta.to.shared.u64 t, %1; cvt.u32.u64 %0, t; }" : "=r"(a) : "l"(p));
    return a;
}

// K-major SW128 blocked-atom byte offset (tcgen05 weight/A image)
__host__ __device__ __forceinline__ uint32_t kmaj_off(int row, int col, int atom_rows) {
    uint32_t off = (uint32_t)((row >> 3) + (col >> 6) * atom_rows) * 1024u
                 + (uint32_t)(row & 7) * 128u + (uint32_t)(col & 63) * 2u;
    return off ^ ((off >> 3) & 0x70);
}

// 512-byte-row XOR swizzle for the HMMA smem tiles (conflict-free ldmatrix)
__device__ __forceinline__ uint32_t swz(uint32_t off) {
    return off ^ ((off >> 5) & 0x70);
}

// pack 8 fp32 -> 8 fp16 (one uint4); identical rounding to __floats2half2_rn
__device__ __forceinline__ uint4 cvt8h(float4 a, float4 b) {
    __half2 h0 = __floats2half2_rn(a.x, a.y), h1 = __floats2half2_rn(a.z, a.w);
    __half2 h2 = __floats2half2_rn(b.x, b.y), h3 = __floats2half2_rn(b.z, b.w);
    uint4 r;
    r.x = *reinterpret_cast<uint32_t*>(&h0);
    r.y = *reinterpret_cast<uint32_t*>(&h1);
    r.z = *reinterpret_cast<uint32_t*>(&h2);
    r.w = *reinterpret_cast<uint32_t*>(&h3);
    return r;
}

// ---------------- fused prep kernel: x->fp16 image (wide) + weight images ----------------
__global__ void prep_all_kernel(const float* __restrict__ x, int n_elem, int nx_blocks,
                                const float* __restrict__ W1, const float* __restrict__ W2) {
    int b = blockIdx.x;
    if (b < nx_blocks) {
        int i = b * 256 + threadIdx.x;             // index of 8-float group
        if (8 * i < n_elem) {
            const float4* xp = reinterpret_cast<const float4*>(x) + 2 * (size_t)i;
            float4 a = xp[0], c = xp[1];
            reinterpret_cast<uint4*>(g_xh)[i] = cvt8h(a, c);
        }
    } else {
        int t = (b - nx_blocks) * 256 + threadIdx.x;
        if (t < HIDDEN * 2 * IN_DIM) {                      // W1^T: n in [0,256), k in [0,256)
            int n = t >> 8, k = t & 255;
            __half v = __float2half_rn(W1[k * HIDDEN + n]);
            g_w1h[n * 256 + k] = v;
            *reinterpret_cast<__half*>(g_w1t + kmaj_off(n, k, 32)) = v;
        } else if (t < HIDDEN * 2 * IN_DIM + OUT_DIM * HIDDEN) {
            int t2 = t - HIDDEN * 2 * IN_DIM;               // W2^T: n in [0,64), k in [0,256)
            int n = t2 >> 8, k = t2 & 255;
            __half v = __float2half_rn(W2[k * OUT_DIM + n]);
            g_w2h[n * 256 + k] = v;
            *reinterpret_cast<__half*>(g_w2t + kmaj_off(n, k, 8)) = v;
        }
    }
}

// ============================================================================
// PATH A: legacy HMMA fallback (launched only when tcgen05 is unavailable)
// ============================================================================

__device__ __forceinline__ void ldsm_x4(uint32_t& r0, uint32_t& r1, uint32_t& r2, uint32_t& r3, uint32_t a) {
    asm volatile("ldmatrix.sync.aligned.m8n8.x4.shared.b16 {%0,%1,%2,%3}, [%4];"
                 : "=r"(r0), "=r"(r1), "=r"(r2), "=r"(r3) : "r"(a));
}
__device__ __forceinline__ void ldsm_x2(uint32_t& r0, uint32_t& r1, uint32_t a) {
    asm volatile("ldmatrix.sync.aligned.m8n8.x2.shared.b16 {%0,%1}, [%2];"
                 : "=r"(r0), "=r"(r1) : "r"(a));
}
__device__ __forceinline__ void mma16816(float* c, uint32_t a0, uint32_t a1, uint32_t a2, uint32_t a3,
                                         uint32_t b0, uint32_t b1) {
    asm volatile("mma.sync.aligned.m16n8k16.row.col.f32.f16.f16.f32 "
                 "{%0,%1,%2,%3}, {%4,%5,%6,%7}, {%8,%9}, {%0,%1,%2,%3};"
                 : "+f"(c[0]), "+f"(c[1]), "+f"(c[2]), "+f"(c[3])
                 : "r"(a0), "r"(a1), "r"(a2), "r"(a3), "r"(b0), "r"(b1));
}

#define HO_W1   0
#define HO_W2   131072
#define HO_A    163840
#define HO_H    196608
#define HO_B1   229376
#define HO_B2   230400
#define HMMA_SMEM (230656 + 1024)

__global__ void __launch_bounds__(256, 1)
edgeffn_hmma(const int* __restrict__ ei, const float* __restrict__ b1g,
             const float* __restrict__ b2g, float* __restrict__ out, int E) {
#if !HAS_TCGEN05
    extern __shared__ char smem_raw[];
    uint32_t raw = smem_u32(smem_raw);
    uint32_t sb = (raw + 1023u) & ~1023u;
    char* smem = smem_raw + (sb - raw);
    int tid = threadIdx.x;
    int lane = tid & 31, wid = tid >> 5;

    {
        const uint4* w1g = reinterpret_cast<const uint4*>(g_w1h);
        for (int i = tid; i < 131072 / 16; i += 256)
            *reinterpret_cast<uint4*>(smem + HO_W1 + swz(i * 16)) = w1g[i];
        const uint4* w2g = reinterpret_cast<const uint4*>(g_w2h);
        for (int i = tid; i < 32768 / 16; i += 256)
            *reinterpret_cast<uint4*>(smem + HO_W2 + swz(i * 16)) = w2g[i];
        float* b1s = reinterpret_cast<float*>(smem + HO_B1);
        if (tid < HIDDEN) b1s[tid] = b1g[tid];
        float* b2s = reinterpret_cast<float*>(smem + HO_B2);
        if (tid < OUT_DIM) b2s[tid] = b2g[tid];
    }
    __syncthreads();

    const float* b1s = reinterpret_cast<const float*>(smem + HO_B1);
    const float* b2s = reinterpret_cast<const float*>(smem + HO_B2);
    const int mrow  = (wid & 3) * 16;
    const int ncol  = (wid >> 2) * 128;
    const int ncol2 = (wid >> 2) * 32;
    int ntiles = (E + 63) >> 6;

    for (int tile = blockIdx.x; tile < ntiles; tile += gridDim.x) {
        {
            int r = tid >> 2, q = tid & 3;
            int e = tile * 64 + r;
            int si = 0, di = 0;
            if (e < E) { si = ei[e]; di = ei[E + e]; }
            const uint4* sp = reinterpret_cast<const uint4*>(g_xh + (size_t)si * IN_DIM);
            const uint4* dp = reinterpret_cast<const uint4*>(g_xh + (size_t)di * IN_DIM);
            #pragma unroll
            for (int j = 0; j < 4; j++) {
                int c = q * 4 + j;
                *reinterpret_cast<uint4*>(smem + HO_A + swz(r * 512 + c * 16)) = sp[c];
                *reinterpret_cast<uint4*>(smem + HO_A + swz(r * 512 + 256 + c * 16)) = dp[c];
            }
        }
        __syncthreads();

        float acc[16][4];
        #pragma unroll
        for (int nt = 0; nt < 16; nt++)
            #pragma unroll
            for (int j = 0; j < 4; j++) acc[nt][j] = 0.0f;

        #pragma unroll
        for (int kt = 0; kt < 16; kt++) {
            uint32_t a0, a1, a2, a3;
            {
                uint32_t arow = mrow + (lane & 15);
                uint32_t aoff = swz(arow * 512 + kt * 32 + ((lane >> 4) << 4));
                ldsm_x4(a0, a1, a2, a3, sb + HO_A + aoff);
            }
            #pragma unroll
            for (int nt = 0; nt < 16; nt++) {
                uint32_t brow = ncol + nt * 8 + (lane & 7);
                uint32_t boff = swz(brow * 512 + kt * 32 + ((lane & 8) << 1));
                uint32_t bb0, bb1;
                ldsm_x2(bb0, bb1, sb + HO_W1 + boff);
                mma16816(acc[nt], a0, a1, a2, a3, bb0, bb1);
            }
        }

        #pragma unroll
        for (int nt = 0; nt < 16; nt++) {
            int col = ncol + nt * 8 + 2 * (lane & 3);
            int row0 = mrow + (lane >> 2);
            float v0 = fmaxf(acc[nt][0] + b1s[col], 0.0f);
            float v1 = fmaxf(acc[nt][1] + b1s[col + 1], 0.0f);
            __half2 h01 = __floats2half2_rn(v0, v1);
            *reinterpret_cast<uint32_t*>(smem + HO_H + swz(row0 * 512 + col * 2)) =
                *reinterpret_cast<uint32_t*>(&h01);
            float v2 = fmaxf(acc[nt][2] + b1s[col], 0.0f);
            float v3 = fmaxf(acc[nt][3] + b1s[col + 1], 0.0f);
            __half2 h23 = __floats2half2_rn(v2, v3);
            *reinterpret_cast<uint32_t*>(smem + HO_H + swz((row0 + 8) * 512 + col * 2)) =
                *reinterpret_cast<uint32_t*>(&h23);
        }
        __syncthreads();

        float acc2[4][4];
        #pragma unroll
        for (int nt = 0; nt < 4; nt++)
            #pragma unroll
            for (int j = 0; j < 4; j++) acc2[nt][j] = 0.0f;

        #pragma unroll
        for (int kt = 0; kt < 16; kt++) {
            uint32_t a0, a1, a2, a3;
            {
                uint32_t arow = mrow + (lane & 15);
                uint32_t aoff = swz(arow * 512 + kt * 32 + ((lane >> 4) << 4));
                ldsm_x4(a0, a1, a2, a3, sb + HO_H + aoff);
            }
            #pragma unroll
            for (int nt = 0; nt < 4; nt++) {
                uint32_t brow = ncol2 + nt * 8 + (lane & 7);
                uint32_t boff = swz(brow * 512 + kt * 32 + ((lane & 8) << 1));
                uint32_t bb0, bb1;
                ldsm_x2(bb0, bb1, sb + HO_W2 + boff);
                mma16816(acc2[nt], a0, a1, a2, a3, bb0, bb1);
            }
        }

        #pragma unroll
        for (int nt = 0; nt < 4; nt++) {
            int col = ncol2 + nt * 8 + 2 * (lane & 3);
            int row0 = mrow + (lane >> 2);
            int e0 = tile * 64 + row0;
            if (e0 < E) {
                float2 v; v.x = acc2[nt][0] + b2s[col]; v.y = acc2[nt][1] + b2s[col + 1];
                *reinterpret_cast<float2*>(out + (size_t)e0 * OUT_DIM + col) = v;
            }
            int e1 = e0 + 8;
            if (e1 < E) {
                float2 v; v.x = acc2[nt][2] + b2s[col]; v.y = acc2[nt][3] + b2s[col + 1];
                *reinterpret_cast<float2*>(out + (size_t)e1 * OUT_DIM + col) = v;
            }
        }
        __syncthreads();
    }
#endif
}

// ============================================================================
// PATH B: tcgen05 — R15 champion; warps 0-3 epi uses 4-deep LDTM issue
// ============================================================================

#if HAS_TCGEN05
__device__ __forceinline__ uint32_t elect_one() {
    uint32_t p;
    asm volatile("{ .reg .pred p; elect.sync _|p, 0xFFFFFFFF; selp.b32 %0, 1, 0, p; }" : "=r"(p));
    return p;
}
#define TC_ALLOC(sa, n)   asm volatile("tcgen05.alloc.cta_group::1.sync.aligned.shared::cta.b32 [%0], %1;" :: "r"(sa), "r"(n) : "memory")
#define TC_DEALLOC(t, n)  asm volatile("tcgen05.dealloc.cta_group::1.sync.aligned.b32 %0, %1;" :: "r"(t), "r"(n))
#define TC_RELINQ()       asm volatile("tcgen05.relinquish_alloc_permit.cta_group::1.sync.aligned;")
#define TC_WAIT_LD()      asm volatile("tcgen05.wait::ld.sync.aligned;" ::: "memory")
#define TC_WAIT_ST()      asm volatile("tcgen05.wait::st.sync.aligned;" ::: "memory")
#define TC_FENCE_BEFORE() asm volatile("tcgen05.fence::before_thread_sync;" ::: "memory")
#define TC_FENCE_AFTER()  asm volatile("tcgen05.fence::after_thread_sync;" ::: "memory")
#define TC_COMMIT(mb)     asm volatile("tcgen05.commit.cta_group::1.mbarrier::arrive::one.shared::cluster.b64 [%0];" :: "r"(mb) : "memory")
#define MBAR_INIT(mb, c)  asm volatile("mbarrier.init.shared.b64 [%0], %1;" :: "r"(mb), "r"(c) : "memory")
#define MBAR_INVAL(mb)    asm volatile("mbarrier.inval.shared.b64 [%0];" :: "r"(mb) : "memory")
#define FENCE_PROXY_ASYNC() asm volatile("fence.proxy.async.shared::cta;" ::: "memory")
#define BAR_SYNC(id, n)   asm volatile("bar.sync %0, %1;" :: "r"(id), "r"(n) : "memory")

#define MBAR_WAIT(mb, ph) do {                                                        \
    uint32_t _mb = (mb); uint32_t _p = (ph); uint32_t _done;                          \
    asm volatile("{ .reg .pred p; mbarrier.try_wait.parity.acquire.cta.shared::cta.b64 p, [%1], %2; selp.b32 %0, 1, 0, p; }" \
        : "=r"(_done) : "r"(_mb), "r"(_p) : "memory");                                \
    if (!_done) {                                                                     \
        asm volatile("{ .reg .pred P1; WL_%=: mbarrier.try_wait.parity.acquire.cta.shared::cta.b64 P1, [%0], %1, 0x989680; @P1 bra.uni WD_%=; bra.uni WL_%=; WD_%=: }" \
            :: "r"(_mb), "r"(_p) : "memory");                                         \
    }                                                                                 \
} while (0)

#define TC_LD_X32(r, ta)                                                              \
    asm volatile("tcgen05.ld.sync.aligned.32x32b.x32.b32 "                            \
        "{%0,%1,%2,%3,%4,%5,%6,%7,%8,%9,%10,%11,%12,%13,%14,%15,"                     \
        "%16,%17,%18,%19,%20,%21,%22,%23,%24,%25,%26,%27,%28,%29,%30,%31}, [%32];"    \
        : "=r"((r)[0]),"=r"((r)[1]),"=r"((r)[2]),"=r"((r)[3]),"=r"((r)[4]),"=r"((r)[5]),"=r"((r)[6]),"=r"((r)[7]), \
          "=r"((r)[8]),"=r"((r)[9]),"=r"((r)[10]),"=r"((r)[11]),"=r"((r)[12]),"=r"((r)[13]),"=r"((r)[14]),"=r"((r)[15]), \
          "=r"((r)[16]),"=r"((r)[17]),"=r"((r)[18]),"=r"((r)[19]),"=r"((r)[20]),"=r"((r)[21]),"=r"((r)[22]),"=r"((r)[23]), \
          "=r"((r)[24]),"=r"((r)[25]),"=r"((r)[26]),"=r"((r)[27]),"=r"((r)[28]),"=r"((r)[29]),"=r"((r)[30]),"=r"((r)[31]) \
        : "r"(ta))

#define TC_ST_X16(ta, r)                                                              \
    asm volatile("tcgen05.st.sync.aligned.32x32b.x16.b32 [%0], "                      \
        "{%1,%2,%3,%4,%5,%6,%7,%8,%9,%10,%11,%12,%13,%14,%15,%16};"                   \
        :: "r"(ta),                                                                   \
           "r"((r)[0]),"r"((r)[1]),"r"((r)[2]),"r"((r)[3]),"r"((r)[4]),"r"((r)[5]),"r"((r)[6]),"r"((r)[7]), \
           "r"((r)[8]),"r"((r)[9]),"r"((r)[10]),"r"((r)[11]),"r"((r)[12]),"r"((r)[13]),"r"((r)[14]),"r"((r)[15]) \
        : "memory")

static constexpr uint64_t DESC_BASE =
    (uint64_t(2) << 61) | (uint64_t(1) << 46) | (uint64_t(64) << 32) | (uint64_t(1) << 16);
__device__ __forceinline__ uint64_t make_desc(uint32_t saddr) {
    return DESC_BASE | ((uint64_t)(saddr >> 4) & 0x3FFF);
}
__device__ __forceinline__ void mma_f16_ss(uint32_t d, uint64_t a, uint64_t b, uint32_t idesc, uint32_t acc) {
    asm volatile(
        "{ .reg .pred p; setp.ne.u32 p, %5, 0;\n\t"
        "tcgen05.mma.cta_group::1.kind::f16 [%0], %1, %2, %3, {%4,%4,%4,%4}, p; }"
        :: "r"(d), "l"(a), "l"(b), "r"(idesc), "r"(0u), "r"(acc) : "memory");
}
__device__ __forceinline__ void mma_f16_ts(uint32_t d, uint32_t a, uint64_t b, uint32_t idesc, uint32_t acc) {
    asm volatile(
        "{ .reg .pred p; setp.ne.u32 p, %5, 0;\n\t"
        "tcgen05.mma.cta_group::1.kind::f16 [%0], [%1], %2, %3, {%4,%4,%4,%4}, p; }"
        :: "r"(d), "r"(a), "l"(b), "r"(idesc), "r"(0u), "r"(acc) : "memory");
}
// N=128 half for GEMM1; N=64 for GEMM2. fp32 accum (dtype=1<<4), fp16 in, M=128.
static constexpr uint32_t IDESC1H = (1u << 4) | ((128 / 8) << 17) | ((128 / 16) << 24);
static constexpr uint32_t IDESC2  = (1u << 4) | ((OUT_DIM / 8) << 17) | ((128 / 16) << 24);

// full GEMM1: h0 (src+dst) commit MBA; h1 (src+dst) commit MBB
__device__ __forceinline__ void issue_mma1(uint32_t TD1, uint64_t dA_src, uint64_t dA_dst,
                                           uint64_t dW1, uint64_t dW1h, uint32_t mba, uint32_t mbb) {
    #pragma unroll
    for (int s = 0; s < 8; s++)
        mma_f16_ss(TD1, dA_src + ((s >> 2) * 1024 + (s & 3) * 2),
                        dW1 + ((s >> 2) * 2048 + (s & 3) * 2), IDESC1H, s > 0);
    #pragma unroll
    for (int s = 0; s < 8; s++)
        mma_f16_ss(TD1, dA_dst + ((s >> 2) * 1024 + (s & 3) * 2),
                        dW1 + ((2 + (s >> 2)) * 2048 + (s & 3) * 2), IDESC1H, 1);
    TC_COMMIT(mba);
    #pragma unroll
    for (int s = 0; s < 8; s++)
        mma_f16_ss(TD1 + 128, dA_src + ((s >> 2) * 1024 + (s & 3) * 2),
                        dW1h + ((s >> 2) * 2048 + (s & 3) * 2), IDESC1H, s > 0);
    #pragma unroll
    for (int s = 0; s < 8; s++)
        mma_f16_ss(TD1 + 128, dA_dst + ((s >> 2) * 1024 + (s & 3) * 2),
                        dW1h + ((2 + (s >> 2)) * 2048 + (s & 3) * 2), IDESC1H, 1);
    TC_COMMIT(mbb);
}
#endif // HAS_TCGEN05

// tcgen05 SMEM layout
#define TO_W1   0
#define TO_W2   131072
#define TO_SRC  163840
#define TO_DST  196608
#define TO_B1   229376
#define TO_B2   230400
#define TO_TM   230656
#define TO_MBA  230664
#define TO_MBB  230672
#define TO_MBC  230680
#define TC_SMEM (230688 + 1024)

#if HAS_TCGEN05
// Coalesced full-tile gather (prologue): 16 lanes per 256B row.
__device__ __forceinline__ void gather_tile_coalesced(char* smem, const int* __restrict__ edge_index,
                                                      int tile_base, int E, int gtid) {
    int g = gtid >> 4, sub = gtid & 15;
    int idx[16];
    uint4 reg[16];
    #pragma unroll
    for (int p = 0; p < 16; p++) {
        int e = tile_base + p * 8 + g;
        idx[p] = (e < E) ? edge_index[e] : 0;
    }
    #pragma unroll
    for (int p = 0; p < 16; p++)
        reg[p] = *reinterpret_cast<const uint4*>(g_xh + (size_t)idx[p] * IN_DIM + sub * 8);
    #pragma unroll
    for (int p = 0; p < 16; p++)
        *reinterpret_cast<uint4*>(smem + TO_SRC + kmaj_off(p * 8 + g, sub * 8, 16)) = reg[p];
    #pragma unroll
    for (int p = 0; p < 16; p++) {
        int e = tile_base + p * 8 + g;
        idx[p] = (e < E) ? edge_index[E + e] : 0;
    }
    #pragma unroll
    for (int p = 0; p < 16; p++)
        reg[p] = *reinterpret_cast<const uint4*>(g_xh + (size_t)idx[p] * IN_DIM + sub * 8);
    #pragma unroll
    for (int p = 0; p < 16; p++)
        *reinterpret_cast<uint4*>(smem + TO_DST + kmaj_off(p * 8 + g, sub * 8, 16)) = reg[p];
}
#endif

__global__ void __launch_bounds__(256, 1)
edgeffn_tc(const int* __restrict__ edge_index, const float* __restrict__ b1,
           const float* __restrict__ b2, float* __restrict__ out, int E) {
#if HAS_TCGEN05
    extern __shared__ char smem_raw[];
    uint32_t raw = smem_u32(smem_raw);
    uint32_t sb = (raw + 1023u) & ~1023u;
    char* smem = smem_raw + (sb - raw);
    int tid = threadIdx.x, wid = tid >> 5;
    const bool lowg = (wid < 4);           // warps 0-3: epi h1 + GEMM issue + out-epi
    const int  gtid = tid & 127;

    if (wid == 0) { TC_ALLOC(sb + TO_TM, 512); TC_RELINQ(); }
    if (tid == 0) {
        MBAR_INIT(sb + TO_MBA, 1); MBAR_INIT(sb + TO_MBB, 1); MBAR_INIT(sb + TO_MBC, 1);
    }

    // stage weights + biases (all 256 threads, once)
    {
        const uint4* w1g = reinterpret_cast<const uint4*>(g_w1t);
        uint4* w1s = reinterpret_cast<uint4*>(smem + TO_W1);
        for (int i = tid; i < 131072 / 16; i += 256) w1s[i] = w1g[i];
        const uint4* w2g = reinterpret_cast<const uint4*>(g_w2t);
        uint4* w2s = reinterpret_cast<uint4*>(smem + TO_W2);
        for (int i = tid; i < 32768 / 16; i += 256) w2s[i] = w2g[i];
        float* b1s = reinterpret_cast<float*>(smem + TO_B1);
        if (tid < HIDDEN) b1s[tid] = b1[tid];
        float* b2s = reinterpret_cast<float*>(smem + TO_B2);
        if (tid < OUT_DIM) b2s[tid] = b2[tid];
    }

    uint32_t tmem;
    int ntiles = (E + 127) >> 7;
    bool has_work = (blockIdx.x < ntiles);

    // ---- prologue gather of tile 0 (warps 4-7, coalesced) ----
    if (!lowg && has_work) {
        gather_tile_coalesced(smem, edge_index, blockIdx.x * 128, E, gtid);
        FENCE_PROXY_ASYNC();
    }
    __syncthreads();
    asm volatile("ld.shared.b32 %0, [%1];" : "=r"(tmem) : "r"(sb + TO_TM));

    const uint32_t TD1 = tmem, TH = tmem + 256, TD2 = tmem + 384;
    const uint64_t dA_src = make_desc(sb + TO_SRC);
    const uint64_t dA_dst = make_desc(sb + TO_DST);
    const uint64_t dW1    = make_desc(sb + TO_W1);     // N rows 0-127
    const uint64_t dW1h   = dW1 + 1024;                // N rows 128-255
    const uint64_t dW2    = make_desc(sb + TO_W2);
    const float* b1s = reinterpret_cast<const float*>(smem + TO_B1);
    const float* b2s = reinterpret_cast<const float*>(smem + TO_B2);
    const uint32_t woff = (uint32_t)(wid & 3) << 21;

    // ---- prologue: issue MMA1(0) ----
    if (has_work && wid == 0 && elect_one()) {
        TC_FENCE_AFTER();
        issue_mma1(TD1, dA_src, dA_dst, dW1, dW1h, sb + TO_MBA, sb + TO_MBB);
    }

    uint32_t ph = 0;

    if (lowg) {
        // ================= warps 0-3: epi h1 (4-deep LDTM), issue, out-epi =================
        for (int tile = blockIdx.x; tile < ntiles; tile += gridDim.x) {
            MBAR_WAIT(sb + TO_MBB, ph);
            TC_FENCE_AFTER();
            {
                // issue ALL four x32 loads up-front, wait once, process both passes
                uint32_t ra0[32], rb0[32], ra1[32], rb1[32];
                TC_LD_X32(ra0, TD1 + 128);
                TC_LD_X32(rb0, TD1 + 160);
                TC_LD_X32(ra1, TD1 + 192);
                TC_LD_X32(rb1, TD1 + 224);
                TC_WAIT_LD();
                #pragma unroll
                for (int pr = 0; pr < 2; pr++) {
                    int c0 = 128 + pr * 64;
                    const uint32_t* ra = pr ? ra1 : ra0;
                    const uint32_t* rb = pr ? rb1 : rb0;
                    uint32_t pa[16], pb[16];
                    #pragma unroll
                    for (int j = 0; j < 16; j++) {
                        float f0 = fmaxf(__uint_as_float(ra[2 * j])     + b1s[c0 + 2 * j],     0.0f);
                        float f1 = fmaxf(__uint_as_float(ra[2 * j + 1]) + b1s[c0 + 2 * j + 1], 0.0f);
                        __half2 hv = __floats2half2_rn(f0, f1);
                        pa[j] = *reinterpret_cast<uint32_t*>(&hv);
                        float g0 = fmaxf(__uint_as_float(rb[2 * j])     + b1s[c0 + 32 + 2 * j],     0.0f);
                        float g1 = fmaxf(__uint_as_float(rb[2 * j + 1]) + b1s[c0 + 32 + 2 * j + 1], 0.0f);
                        __half2 gv = __floats2half2_rn(g0, g1);
                        pb[j] = *reinterpret_cast<uint32_t*>(&gv);
                    }
                    TC_ST_X16(TH + (c0 >> 1) + woff, pa);
                    TC_ST_X16(TH + ((c0 + 32) >> 1) + woff, pb);
                }
            }
            TC_WAIT_ST();
            TC_FENCE_BEFORE();
            BAR_SYNC(0, 256);   // h complete, D1 drained, A(t+1) staged by warps 4-7

            if (wid == 0) {
                TC_FENCE_AFTER();
                if (elect_one()) {
                    // G2 FIRST in queue (TH hazard: epi(t+1) gated by MBA = after G1h0,
                    // which executes after G2 in-order)
                    #pragma unroll
                    for (int s = 0; s < 16; s++)
                        mma_f16_ts(TD2, TH + s * 8, dW2 + ((s >> 2) * 512 + (s & 3) * 2), IDESC2, s > 0);
                    TC_COMMIT(sb + TO_MBC);
                    if (tile + gridDim.x < ntiles)
                        issue_mma1(TD1, dA_src, dA_dst, dW1, dW1h, sb + TO_MBA, sb + TO_MBB);
                }
            }

            // ---- out-epi: D2 + b2 -> gmem ----
            int e = tile * 128 + gtid;
            MBAR_WAIT(sb + TO_MBC, ph);
            TC_FENCE_AFTER();
            uint32_t r0[32], r1[32];
            TC_LD_X32(r0, TD2);
            TC_LD_X32(r1, TD2 + 32);
            TC_WAIT_LD();          // drained before this warp's next BAR_SYNC -> G2(t+1) safe
            if (e < E) {
                float4* orow = reinterpret_cast<float4*>(out + (size_t)e * OUT_DIM);
                #pragma unroll
                for (int q = 0; q < 8; q++) {
                    float4 v;
                    v.x = __uint_as_float(r0[4 * q])     + b2s[4 * q];
                    v.y = __uint_as_float(r0[4 * q + 1]) + b2s[4 * q + 1];
                    v.z = __uint_as_float(r0[4 * q + 2]) + b2s[4 * q + 2];
                    v.w = __uint_as_float(r0[4 * q + 3]) + b2s[4 * q + 3];
                    orow[q] = v;
                }
                #pragma unroll
                for (int q = 0; q < 8; q++) {
                    float4 v;
                    v.x = __uint_as_float(r1[4 * q])     + b2s[32 + 4 * q];
                    v.y = __uint_as_float(r1[4 * q + 1]) + b2s[32 + 4 * q + 1];
                    v.z = __uint_as_float(r1[4 * q + 2]) + b2s[32 + 4 * q + 2];
                    v.w = __uint_as_float(r1[4 * q + 3]) + b2s[32 + 4 * q + 3];
                    orow[8 + q] = v;
                }
            }
            ph ^= 1;
        }
    } else {
        // ================= warps 4-7: epi h0 + gather (unchanged R15) =================
        const int g = gtid >> 4, sub = gtid & 15;
        for (int tile = blockIdx.x; tile < ntiles; tile += gridDim.x) {
            int ntile = tile + gridDim.x;
            bool gnext = (ntile < ntiles);
            int nbase = ntile * 128;

            // prefetch edge indices for t+1 (no A dependency; covers idx latency)
            int sidx[16], didx[16];
            if (gnext) {
                #pragma unroll
                for (int p = 0; p < 16; p++) {
                    int ne = nbase + p * 8 + g;
                    sidx[p] = (ne < E) ? edge_index[ne] : 0;
                    didx[p] = (ne < E) ? edge_index[E + ne] : 0;
                }
            }

            // ---- epi half0 (cols 0-127), gated by MBA (fires 1024 cyc before MBB) ----
            MBAR_WAIT(sb + TO_MBA, ph);
            TC_FENCE_AFTER();
            #pragma unroll
            for (int pr = 0; pr < 2; pr++) {
                int c0 = pr * 64;
                uint32_t ra[32], rb[32];
                TC_LD_X32(ra, TD1 + c0);
                TC_LD_X32(rb, TD1 + c0 + 32);
                TC_WAIT_LD();
                uint32_t pa[16], pb[16];
                #pragma unroll
                for (int j = 0; j < 16; j++) {
                    float f0 = fmaxf(__uint_as_float(ra[2 * j])     + b1s[c0 + 2 * j],     0.0f);
                    float f1 = fmaxf(__uint_as_float(ra[2 * j + 1]) + b1s[c0 + 2 * j + 1], 0.0f);
                    __half2 hv = __floats2half2_rn(f0, f1);
                    pa[j] = *reinterpret_cast<uint32_t*>(&hv);
                    float g0 = fmaxf(__uint_as_float(rb[2 * j])     + b1s[c0 + 32 + 2 * j],     0.0f);
                    float g1 = fmaxf(__uint_as_float(rb[2 * j + 1]) + b1s[c0 + 32 + 2 * j + 1], 0.0f);
                    __half2 gv = __floats2half2_rn(g0, g1);
                    pb[j] = *reinterpret_cast<uint32_t*>(&gv);
                }
                TC_ST_X16(TH + (c0 >> 1) + woff, pa);
                TC_ST_X16(TH + ((c0 + 32) >> 1) + woff, pb);
            }
            TC_WAIT_ST();
            TC_FENCE_BEFORE();

            // ---- gather A(t+1): after MBB (A free); LDG latency hidden by epi above ----
            MBAR_WAIT(sb + TO_MBB, ph);
            if (gnext) {
                uint4 reg[16];
                #pragma unroll
                for (int p = 0; p < 16; p++)
                    reg[p] = *reinterpret_cast<const uint4*>(g_xh + (size_t)sidx[p] * IN_DIM + sub * 8);
                #pragma unroll
                for (int p = 0; p < 16; p++)
                    *reinterpret_cast<uint4*>(smem + TO_SRC + kmaj_off(p * 8 + g, sub * 8, 16)) = reg[p];
                #pragma unroll
                for (int p = 0; p < 16; p++)
                    reg[p] = *reinterpret_cast<const uint4*>(g_xh + (size_t)didx[p] * IN_DIM + sub * 8);
                #pragma unroll
                for (int p = 0; p < 16; p++)
                    *reinterpret_cast<uint4*>(smem + TO_DST + kmaj_off(p * 8 + g, sub * 8, 16)) = reg[p];
                FENCE_PROXY_ASYNC();
            }
            BAR_SYNC(0, 256);   // joins warps 0-3's bar; A(t+1) visible to warp0's MMA issue
            ph ^= 1;
        }
    }

    __syncthreads();
    if (tid == 0) {
        MBAR_INVAL(sb + TO_MBA); MBAR_INVAL(sb + TO_MBB); MBAR_INVAL(sb + TO_MBC);
    }
    __syncthreads();
    if (wid == 0) TC_DEALLOC(tmem, 512);
#endif
}

// ---------------- launch ----------------
extern "C" void kernel_launch(void* const* d_in, const int* in_sizes, int n_in,
                              void* d_out, int out_size) {
    const float* x  = (const float*)d_in[0];
    const int* ei   = (const int*)d_in[1];
    const float* W1 = (const float*)d_in[2];
    const float* b1 = (const float*)d_in[3];
    const float* W2 = (const float*)d_in[4];
    const float* b2 = (const float*)d_in[5];
    float* out = (float*)d_out;

    int x_elems = in_sizes[0];
    int E = in_sizes[1] / 2;

    // Fused prep: x-conversion blocks (8 floats/thread) + weight-image blocks.
    int ngroups = (x_elems + 7) / 8;
    int nx_blocks = (ngroups + 255) / 256;
    int wtot = HIDDEN * 2 * IN_DIM + OUT_DIM * HIDDEN;   // 81920
    int nw_blocks = (wtot + 255) / 256;                  // 320
    prep_all_kernel<<<nx_blocks + nw_blocks, 256>>>(x, x_elems, nx_blocks, W1, W2);

    int dev = 0, nsm = 148;
    cudaGetDevice(&dev);
    cudaDeviceGetAttribute(&nsm, cudaDevAttrMultiProcessorCount, dev);

    // Launch only the kernel whose body survived compilation (the other is a
    // near-empty stub with few registers). Decided at capture time: deterministic.
    cudaFuncAttributes attr{};
    cudaFuncGetAttributes(&attr, edgeffn_tc);
    if (attr.numRegs > 64) {
        cudaFuncSetAttribute(edgeffn_tc, cudaFuncAttributeMaxDynamicSharedMemorySize, TC_SMEM);
        edgeffn_tc<<<nsm, 256, TC_SMEM>>>(ei, b1, b2, out, E);
    } else {
        cudaFuncSetAttribute(edgeffn_hmma, cudaFuncAttributeMaxDynamicSharedMemorySize, HMMA_SMEM);
        edgeffn_hmma<<<nsm, 256, HMMA_SMEM>>>(ei, b1, b2, out, E);
    }
}

// round 17
// speedup vs baseline: 1.0034x; 1.0034x over previous
#include <cuda_runtime.h>
#include <cuda_fp16.h>
#include <cstdint>

// ---------------- problem constants ----------------
#define IN_DIM   128
#define HIDDEN   256
#define OUT_DIM  64
#define N_NODES_MAX 100000

// Does this device-compile pass support tcgen05? (arch-specific or family target)
#if defined(__CUDA_ARCH__)
#  if defined(__CUDA_ARCH_FEAT_SM103_ALL) || defined(__CUDA_ARCH_FEAT_SM100_ALL) || \
      (defined(__CUDA_ARCH_FAMILY_SPECIFIC__) && (__CUDA_ARCH_FAMILY_SPECIFIC__ >= 1000))
#    define HAS_TCGEN05 1
#  else
#    define HAS_TCGEN05 0
#  endif
#else
#  define HAS_TCGEN05 0
#endif

// ---------------- device scratch (no allocs allowed) ----------------
__device__ __half        g_xh[(size_t)N_NODES_MAX * IN_DIM];   // 25.6 MB fp16 node features
__device__ unsigned char g_w1t[HIDDEN * (2 * IN_DIM) * 2];     // SW128 image for tcgen05 path
__device__ unsigned char g_w2t[OUT_DIM * HIDDEN * 2];          // SW128 image for tcgen05 path
__device__ __half        g_w1h[HIDDEN * (2 * IN_DIM)];         // [n][k] linear fp16 (HMMA path)
__device__ __half        g_w2h[OUT_DIM * HIDDEN];              // [n][k] linear fp16 (HMMA path)

// ---------------- common helpers ----------------
__device__ __forceinline__ uint32_t smem_u32(const void* p) {
    uint32_t a;
    asm("{ .reg .u64 t; cvta.to.shared.u64 t, %1; cvt.u32.u64 %0, t; }" : "=r"(a) : "l"(p));
    return a;
}

// K-major SW128 blocked-atom byte offset (tcgen05 weight/A image)
__host__ __device__ __forceinline__ uint32_t kmaj_off(int row, int col, int atom_rows) {
    uint32_t off = (uint32_t)((row >> 3) + (col >> 6) * atom_rows) * 1024u
                 + (uint32_t)(row & 7) * 128u + (uint32_t)(col & 63) * 2u;
    return off ^ ((off >> 3) & 0x70);
}

// 512-byte-row XOR swizzle for the HMMA smem tiles (conflict-free ldmatrix)
__device__ __forceinline__ uint32_t swz(uint32_t off) {
    return off ^ ((off >> 5) & 0x70);
}

// pack 8 fp32 -> 8 fp16 (one uint4); identical rounding to __floats2half2_rn
__device__ __forceinline__ uint4 cvt8h(float4 a, float4 b) {
    __half2 h0 = __floats2half2_rn(a.x, a.y), h1 = __floats2half2_rn(a.z, a.w);
    __half2 h2 = __floats2half2_rn(b.x, b.y), h3 = __floats2half2_rn(b.z, b.w);
    uint4 r;
    r.x = *reinterpret_cast<uint32_t*>(&h0);
    r.y = *reinterpret_cast<uint32_t*>(&h1);
    r.z = *reinterpret_cast<uint32_t*>(&h2);
    r.w = *reinterpret_cast<uint32_t*>(&h3);
    return r;
}

// ---------------- fused prep kernel: x->fp16 image (wide) + weight images ----------------
__global__ void prep_all_kernel(const float* __restrict__ x, int n_elem, int nx_blocks,
                                const float* __restrict__ W1, const float* __restrict__ W2) {
    int b = blockIdx.x;
    if (b < nx_blocks) {
        int i = b * 256 + threadIdx.x;             // index of 8-float group
        if (8 * i < n_elem) {
            const float4* xp = reinterpret_cast<const float4*>(x) + 2 * (size_t)i;
            float4 a = xp[0], c = xp[1];
            reinterpret_cast<uint4*>(g_xh)[i] = cvt8h(a, c);
        }
    } else {
        int t = (b - nx_blocks) * 256 + threadIdx.x;
        if (t < HIDDEN * 2 * IN_DIM) {                      // W1^T: n in [0,256), k in [0,256)
            int n = t >> 8, k = t & 255;
            __half v = __float2half_rn(W1[k * HIDDEN + n]);
            g_w1h[n * 256 + k] = v;
            *reinterpret_cast<__half*>(g_w1t + kmaj_off(n, k, 32)) = v;
        } else if (t < HIDDEN * 2 * IN_DIM + OUT_DIM * HIDDEN) {
            int t2 = t - HIDDEN * 2 * IN_DIM;               // W2^T: n in [0,64), k in [0,256)
            int n = t2 >> 8, k = t2 & 255;
            __half v = __float2half_rn(W2[k * OUT_DIM + n]);
            g_w2h[n * 256 + k] = v;
            *reinterpret_cast<__half*>(g_w2t + kmaj_off(n, k, 8)) = v;
        }
    }
}

// ============================================================================
// PATH A: legacy HMMA fallback (launched only when tcgen05 is unavailable)
// ============================================================================

__device__ __forceinline__ void ldsm_x4(uint32_t& r0, uint32_t& r1, uint32_t& r2, uint32_t& r3, uint32_t a) {
    asm volatile("ldmatrix.sync.aligned.m8n8.x4.shared.b16 {%0,%1,%2,%3}, [%4];"
                 : "=r"(r0), "=r"(r1), "=r"(r2), "=r"(r3) : "r"(a));
}
__device__ __forceinline__ void ldsm_x2(uint32_t& r0, uint32_t& r1, uint32_t a) {
    asm volatile("ldmatrix.sync.aligned.m8n8.x2.shared.b16 {%0,%1}, [%2];"
                 : "=r"(r0), "=r"(r1) : "r"(a));
}
__device__ __forceinline__ void mma16816(float* c, uint32_t a0, uint32_t a1, uint32_t a2, uint32_t a3,
                                         uint32_t b0, uint32_t b1) {
    asm volatile("mma.sync.aligned.m16n8k16.row.col.f32.f16.f16.f32 "
                 "{%0,%1,%2,%3}, {%4,%5,%6,%7}, {%8,%9}, {%0,%1,%2,%3};"
                 : "+f"(c[0]), "+f"(c[1]), "+f"(c[2]), "+f"(c[3])
                 : "r"(a0), "r"(a1), "r"(a2), "r"(a3), "r"(b0), "r"(b1));
}

#define HO_W1   0
#define HO_W2   131072
#define HO_A    163840
#define HO_H    196608
#define HO_B1   229376
#define HO_B2   230400
#define HMMA_SMEM (230656 + 1024)

__global__ void __launch_bounds__(256, 1)
edgeffn_hmma(const int* __restrict__ ei, const float* __restrict__ b1g,
             const float* __restrict__ b2g, float* __restrict__ out, int E) {
#if !HAS_TCGEN05
    extern __shared__ char smem_raw[];
    uint32_t raw = smem_u32(smem_raw);
    uint32_t sb = (raw + 1023u) & ~1023u;
    char* smem = smem_raw + (sb - raw);
    int tid = threadIdx.x;
    int lane = tid & 31, wid = tid >> 5;

    {
        const uint4* w1g = reinterpret_cast<const uint4*>(g_w1h);
        for (int i = tid; i < 131072 / 16; i += 256)
            *reinterpret_cast<uint4*>(smem + HO_W1 + swz(i * 16)) = w1g[i];
        const uint4* w2g = reinterpret_cast<const uint4*>(g_w2h);
        for (int i = tid; i < 32768 / 16; i += 256)
            *reinterpret_cast<uint4*>(smem + HO_W2 + swz(i * 16)) = w2g[i];
        float* b1s = reinterpret_cast<float*>(smem + HO_B1);
        if (tid < HIDDEN) b1s[tid] = b1g[tid];
        float* b2s = reinterpret_cast<float*>(smem + HO_B2);
        if (tid < OUT_DIM) b2s[tid] = b2g[tid];
    }
    __syncthreads();

    const float* b1s = reinterpret_cast<const float*>(smem + HO_B1);
    const float* b2s = reinterpret_cast<const float*>(smem + HO_B2);
    const int mrow  = (wid & 3) * 16;
    const int ncol  = (wid >> 2) * 128;
    const int ncol2 = (wid >> 2) * 32;
    int ntiles = (E + 63) >> 6;

    for (int tile = blockIdx.x; tile < ntiles; tile += gridDim.x) {
        {
            int r = tid >> 2, q = tid & 3;
            int e = tile * 64 + r;
            int si = 0, di = 0;
            if (e < E) { si = ei[e]; di = ei[E + e]; }
            const uint4* sp = reinterpret_cast<const uint4*>(g_xh + (size_t)si * IN_DIM);
            const uint4* dp = reinterpret_cast<const uint4*>(g_xh + (size_t)di * IN_DIM);
            #pragma unroll
            for (int j = 0; j < 4; j++) {
                int c = q * 4 + j;
                *reinterpret_cast<uint4*>(smem + HO_A + swz(r * 512 + c * 16)) = sp[c];
                *reinterpret_cast<uint4*>(smem + HO_A + swz(r * 512 + 256 + c * 16)) = dp[c];
            }
        }
        __syncthreads();

        float acc[16][4];
        #pragma unroll
        for (int nt = 0; nt < 16; nt++)
            #pragma unroll
            for (int j = 0; j < 4; j++) acc[nt][j] = 0.0f;

        #pragma unroll
        for (int kt = 0; kt < 16; kt++) {
            uint32_t a0, a1, a2, a3;
            {
                uint32_t arow = mrow + (lane & 15);
                uint32_t aoff = swz(arow * 512 + kt * 32 + ((lane >> 4) << 4));
                ldsm_x4(a0, a1, a2, a3, sb + HO_A + aoff);
            }
            #pragma unroll
            for (int nt = 0; nt < 16; nt++) {
                uint32_t brow = ncol + nt * 8 + (lane & 7);
                uint32_t boff = swz(brow * 512 + kt * 32 + ((lane & 8) << 1));
                uint32_t bb0, bb1;
                ldsm_x2(bb0, bb1, sb + HO_W1 + boff);
                mma16816(acc[nt], a0, a1, a2, a3, bb0, bb1);
            }
        }

        #pragma unroll
        for (int nt = 0; nt < 16; nt++) {
            int col = ncol + nt * 8 + 2 * (lane & 3);
            int row0 = mrow + (lane >> 2);
            float v0 = fmaxf(acc[nt][0] + b1s[col], 0.0f);
            float v1 = fmaxf(acc[nt][1] + b1s[col + 1], 0.0f);
            __half2 h01 = __floats2half2_rn(v0, v1);
            *reinterpret_cast<uint32_t*>(smem + HO_H + swz(row0 * 512 + col * 2)) =
                *reinterpret_cast<uint32_t*>(&h01);
            float v2 = fmaxf(acc[nt][2] + b1s[col], 0.0f);
            float v3 = fmaxf(acc[nt][3] + b1s[col + 1], 0.0f);
            __half2 h23 = __floats2half2_rn(v2, v3);
            *reinterpret_cast<uint32_t*>(smem + HO_H + swz((row0 + 8) * 512 + col * 2)) =
                *reinterpret_cast<uint32_t*>(&h23);
        }
        __syncthreads();

        float acc2[4][4];
        #pragma unroll
        for (int nt = 0; nt < 4; nt++)
            #pragma unroll
            for (int j = 0; j < 4; j++) acc2[nt][j] = 0.0f;

        #pragma unroll
        for (int kt = 0; kt < 16; kt++) {
            uint32_t a0, a1, a2, a3;
            {
                uint32_t arow = mrow + (lane & 15);
                uint32_t aoff = swz(arow * 512 + kt * 32 + ((lane >> 4) << 4));
                ldsm_x4(a0, a1, a2, a3, sb + HO_H + aoff);
            }
            #pragma unroll
            for (int nt = 0; nt < 4; nt++) {
                uint32_t brow = ncol2 + nt * 8 + (lane & 7);
                uint32_t boff = swz(brow * 512 + kt * 32 + ((lane & 8) << 1));
                uint32_t bb0, bb1;
                ldsm_x2(bb0, bb1, sb + HO_W2 + boff);
                mma16816(acc2[nt], a0, a1, a2, a3, bb0, bb1);
            }
        }

        #pragma unroll
        for (int nt = 0; nt < 4; nt++) {
            int col = ncol2 + nt * 8 + 2 * (lane & 3);
            int row0 = mrow + (lane >> 2);
            int e0 = tile * 64 + row0;
            if (e0 < E) {
                float2 v; v.x = acc2[nt][0] + b2s[col]; v.y = acc2[nt][1] + b2s[col + 1];
                *reinterpret_cast<float2*>(out + (size_t)e0 * OUT_DIM + col) = v;
            }
            int e1 = e0 + 8;
            if (e1 < E) {
                float2 v; v.x = acc2[nt][2] + b2s[col]; v.y = acc2[nt][3] + b2s[col + 1];
                *reinterpret_cast<float2*>(out + (size_t)e1 * OUT_DIM + col) = v;
            }
        }
        __syncthreads();
    }
#endif
}

// ============================================================================
// PATH B: tcgen05 — R15 CHAMPION pipeline (exact)
//   warps 4-7: [idx prefetch] epi half0 (MBA) -> gather-STS A(t+1) (MBB) -> bar
//   warps 0-3: epi half1 (MBB) -> bar -> warp0: G2(t)+G1(t+1) -> out-epi(t)
// ============================================================================

#if HAS_TCGEN05
__device__ __forceinline__ uint32_t elect_one() {
    uint32_t p;
    asm volatile("{ .reg .pred p; elect.sync _|p, 0xFFFFFFFF; selp.b32 %0, 1, 0, p; }" : "=r"(p));
    return p;
}
#define TC_ALLOC(sa, n)   asm volatile("tcgen05.alloc.cta_group::1.sync.aligned.shared::cta.b32 [%0], %1;" :: "r"(sa), "r"(n) : "memory")
#define TC_DEALLOC(t, n)  asm volatile("tcgen05.dealloc.cta_group::1.sync.aligned.b32 %0, %1;" :: "r"(t), "r"(n))
#define TC_RELINQ()       asm volatile("tcgen05.relinquish_alloc_permit.cta_group::1.sync.aligned;")
#define TC_WAIT_LD()      asm volatile("tcgen05.wait::ld.sync.aligned;" ::: "memory")
#define TC_WAIT_ST()      asm volatile("tcgen05.wait::st.sync.aligned;" ::: "memory")
#define TC_FENCE_BEFORE() asm volatile("tcgen05.fence::before_thread_sync;" ::: "memory")
#define TC_FENCE_AFTER()  asm volatile("tcgen05.fence::after_thread_sync;" ::: "memory")
#define TC_COMMIT(mb)     asm volatile("tcgen05.commit.cta_group::1.mbarrier::arrive::one.shared::cluster.b64 [%0];" :: "r"(mb) : "memory")
#define MBAR_INIT(mb, c)  asm volatile("mbarrier.init.shared.b64 [%0], %1;" :: "r"(mb), "r"(c) : "memory")
#define MBAR_INVAL(mb)    asm volatile("mbarrier.inval.shared.b64 [%0];" :: "r"(mb) : "memory")
#define FENCE_PROXY_ASYNC() asm volatile("fence.proxy.async.shared::cta;" ::: "memory")
#define BAR_SYNC(id, n)   asm volatile("bar.sync %0, %1;" :: "r"(id), "r"(n) : "memory")

#define MBAR_WAIT(mb, ph) do {                                                        \
    uint32_t _mb = (mb); uint32_t _p = (ph); uint32_t _done;                          \
    asm volatile("{ .reg .pred p; mbarrier.try_wait.parity.acquire.cta.shared::cta.b64 p, [%1], %2; selp.b32 %0, 1, 0, p; }" \
        : "=r"(_done) : "r"(_mb), "r"(_p) : "memory");                                \
    if (!_done) {                                                                     \
        asm volatile("{ .reg .pred P1; WL_%=: mbarrier.try_wait.parity.acquire.cta.shared::cta.b64 P1, [%0], %1, 0x989680; @P1 bra.uni WD_%=; bra.uni WL_%=; WD_%=: }" \
            :: "r"(_mb), "r"(_p) : "memory");                                         \
    }                                                                                 \
} while (0)

#define TC_LD_X32(r, ta)                                                              \
    asm volatile("tcgen05.ld.sync.aligned.32x32b.x32.b32 "                            \
        "{%0,%1,%2,%3,%4,%5,%6,%7,%8,%9,%10,%11,%12,%13,%14,%15,"                     \
        "%16,%17,%18,%19,%20,%21,%22,%23,%24,%25,%26,%27,%28,%29,%30,%31}, [%32];"    \
        : "=r"((r)[0]),"=r"((r)[1]),"=r"((r)[2]),"=r"((r)[3]),"=r"((r)[4]),"=r"((r)[5]),"=r"((r)[6]),"=r"((r)[7]), \
          "=r"((r)[8]),"=r"((r)[9]),"=r"((r)[10]),"=r"((r)[11]),"=r"((r)[12]),"=r"((r)[13]),"=r"((r)[14]),"=r"((r)[15]), \
          "=r"((r)[16]),"=r"((r)[17]),"=r"((r)[18]),"=r"((r)[19]),"=r"((r)[20]),"=r"((r)[21]),"=r"((r)[22]),"=r"((r)[23]), \
          "=r"((r)[24]),"=r"((r)[25]),"=r"((r)[26]),"=r"((r)[27]),"=r"((r)[28]),"=r"((r)[29]),"=r"((r)[30]),"=r"((r)[31]) \
        : "r"(ta))

#define TC_ST_X16(ta, r)                                                              \
    asm volatile("tcgen05.st.sync.aligned.32x32b.x16.b32 [%0], "                      \
        "{%1,%2,%3,%4,%5,%6,%7,%8,%9,%10,%11,%12,%13,%14,%15,%16};"                   \
        :: "r"(ta),                                                                   \
           "r"((r)[0]),"r"((r)[1]),"r"((r)[2]),"r"((r)[3]),"r"((r)[4]),"r"((r)[5]),"r"((r)[6]),"r"((r)[7]), \
           "r"((r)[8]),"r"((r)[9]),"r"((r)[10]),"r"((r)[11]),"r"((r)[12]),"r"((r)[13]),"r"((r)[14]),"r"((r)[15]) \
        : "memory")

static constexpr uint64_t DESC_BASE =
    (uint64_t(2) << 61) | (uint64_t(1) << 46) | (uint64_t(64) << 32) | (uint64_t(1) << 16);
__device__ __forceinline__ uint64_t make_desc(uint32_t saddr) {
    return DESC_BASE | ((uint64_t)(saddr >> 4) & 0x3FFF);
}
__device__ __forceinline__ void mma_f16_ss(uint32_t d, uint64_t a, uint64_t b, uint32_t idesc, uint32_t acc) {
    asm volatile(
        "{ .reg .pred p; setp.ne.u32 p, %5, 0;\n\t"
        "tcgen05.mma.cta_group::1.kind::f16 [%0], %1, %2, %3, {%4,%4,%4,%4}, p; }"
        :: "r"(d), "l"(a), "l"(b), "r"(idesc), "r"(0u), "r"(acc) : "memory");
}
__device__ __forceinline__ void mma_f16_ts(uint32_t d, uint32_t a, uint64_t b, uint32_t idesc, uint32_t acc) {
    asm volatile(
        "{ .reg .pred p; setp.ne.u32 p, %5, 0;\n\t"
        "tcgen05.mma.cta_group::1.kind::f16 [%0], [%1], %2, %3, {%4,%4,%4,%4}, p; }"
        :: "r"(d), "r"(a), "l"(b), "r"(idesc), "r"(0u), "r"(acc) : "memory");
}
// N=128 half for GEMM1; N=64 for GEMM2. fp32 accum (dtype=1<<4), fp16 in, M=128.
static constexpr uint32_t IDESC1H = (1u << 4) | ((128 / 8) << 17) | ((128 / 16) << 24);
static constexpr uint32_t IDESC2  = (1u << 4) | ((OUT_DIM / 8) << 17) | ((128 / 16) << 24);

// full GEMM1: h0 (src+dst) commit MBA; h1 (src+dst) commit MBB
__device__ __forceinline__ void issue_mma1(uint32_t TD1, uint64_t dA_src, uint64_t dA_dst,
                                           uint64_t dW1, uint64_t dW1h, uint32_t mba, uint32_t mbb) {
    #pragma unroll
    for (int s = 0; s < 8; s++)
        mma_f16_ss(TD1, dA_src + ((s >> 2) * 1024 + (s & 3) * 2),
                        dW1 + ((s >> 2) * 2048 + (s & 3) * 2), IDESC1H, s > 0);
    #pragma unroll
    for (int s = 0; s < 8; s++)
        mma_f16_ss(TD1, dA_dst + ((s >> 2) * 1024 + (s & 3) * 2),
                        dW1 + ((2 + (s >> 2)) * 2048 + (s & 3) * 2), IDESC1H, 1);
    TC_COMMIT(mba);
    #pragma unroll
    for (int s = 0; s < 8; s++)
        mma_f16_ss(TD1 + 128, dA_src + ((s >> 2) * 1024 + (s & 3) * 2),
                        dW1h + ((s >> 2) * 2048 + (s & 3) * 2), IDESC1H, s > 0);
    #pragma unroll
    for (int s = 0; s < 8; s++)
        mma_f16_ss(TD1 + 128, dA_dst + ((s >> 2) * 1024 + (s & 3) * 2),
                        dW1h + ((2 + (s >> 2)) * 2048 + (s & 3) * 2), IDESC1H, 1);
    TC_COMMIT(mbb);
}
#endif // HAS_TCGEN05

// tcgen05 SMEM layout
#define TO_W1   0
#define TO_W2   131072
#define TO_SRC  163840
#define TO_DST  196608
#define TO_B1   229376
#define TO_B2   230400
#define TO_TM   230656
#define TO_MBA  230664
#define TO_MBB  230672
#define TO_MBC  230680
#define TC_SMEM (230688 + 1024)

#if HAS_TCGEN05
// Coalesced full-tile gather (prologue): 16 lanes per 256B row.
__device__ __forceinline__ void gather_tile_coalesced(char* smem, const int* __restrict__ edge_index,
                                                      int tile_base, int E, int gtid) {
    int g = gtid >> 4, sub = gtid & 15;
    int idx[16];
    uint4 reg[16];
    #pragma unroll
    for (int p = 0; p < 16; p++) {
        int e = tile_base + p * 8 + g;
        idx[p] = (e < E) ? edge_index[e] : 0;
    }
    #pragma unroll
    for (int p = 0; p < 16; p++)
        reg[p] = *reinterpret_cast<const uint4*>(g_xh + (size_t)idx[p] * IN_DIM + sub * 8);
    #pragma unroll
    for (int p = 0; p < 16; p++)
        *reinterpret_cast<uint4*>(smem + TO_SRC + kmaj_off(p * 8 + g, sub * 8, 16)) = reg[p];
    #pragma unroll
    for (int p = 0; p < 16; p++) {
        int e = tile_base + p * 8 + g;
        idx[p] = (e < E) ? edge_index[E + e] : 0;
    }
    #pragma unroll
    for (int p = 0; p < 16; p++)
        reg[p] = *reinterpret_cast<const uint4*>(g_xh + (size_t)idx[p] * IN_DIM + sub * 8);
    #pragma unroll
    for (int p = 0; p < 16; p++)
        *reinterpret_cast<uint4*>(smem + TO_DST + kmaj_off(p * 8 + g, sub * 8, 16)) = reg[p];
}
#endif

__global__ void __launch_bounds__(256, 1)
edgeffn_tc(const int* __restrict__ edge_index, const float* __restrict__ b1,
           const float* __restrict__ b2, float* __restrict__ out, int E) {
#if HAS_TCGEN05
    extern __shared__ char smem_raw[];
    uint32_t raw = smem_u32(smem_raw);
    uint32_t sb = (raw + 1023u) & ~1023u;
    char* smem = smem_raw + (sb - raw);
    int tid = threadIdx.x, wid = tid >> 5;
    const bool lowg = (wid < 4);           // warps 0-3: epi h1 + GEMM issue + out-epi
    const int  gtid = tid & 127;

    if (wid == 0) { TC_ALLOC(sb + TO_TM, 512); TC_RELINQ(); }
    if (tid == 0) {
        MBAR_INIT(sb + TO_MBA, 1); MBAR_INIT(sb + TO_MBB, 1); MBAR_INIT(sb + TO_MBC, 1);
    }

    // stage weights + biases (all 256 threads, once)
    {
        const uint4* w1g = reinterpret_cast<const uint4*>(g_w1t);
        uint4* w1s = reinterpret_cast<uint4*>(smem + TO_W1);
        for (int i = tid; i < 131072 / 16; i += 256) w1s[i] = w1g[i];
        const uint4* w2g = reinterpret_cast<const uint4*>(g_w2t);
        uint4* w2s = reinterpret_cast<uint4*>(smem + TO_W2);
        for (int i = tid; i < 32768 / 16; i += 256) w2s[i] = w2g[i];
        float* b1s = reinterpret_cast<float*>(smem + TO_B1);
        if (tid < HIDDEN) b1s[tid] = b1[tid];
        float* b2s = reinterpret_cast<float*>(smem + TO_B2);
        if (tid < OUT_DIM) b2s[tid] = b2[tid];
    }

    uint32_t tmem;
    int ntiles = (E + 127) >> 7;
    bool has_work = (blockIdx.x < ntiles);

    // ---- prologue gather of tile 0 (warps 4-7, coalesced) ----
    if (!lowg && has_work) {
        gather_tile_coalesced(smem, edge_index, blockIdx.x * 128, E, gtid);
        FENCE_PROXY_ASYNC();
    }
    __syncthreads();
    asm volatile("ld.shared.b32 %0, [%1];" : "=r"(tmem) : "r"(sb + TO_TM));

    const uint32_t TD1 = tmem, TH = tmem + 256, TD2 = tmem + 384;
    const uint64_t dA_src = make_desc(sb + TO_SRC);
    const uint64_t dA_dst = make_desc(sb + TO_DST);
    const uint64_t dW1    = make_desc(sb + TO_W1);     // N rows 0-127
    const uint64_t dW1h   = dW1 + 1024;                // N rows 128-255
    const uint64_t dW2    = make_desc(sb + TO_W2);
    const float* b1s = reinterpret_cast<const float*>(smem + TO_B1);
    const float* b2s = reinterpret_cast<const float*>(smem + TO_B2);
    const uint32_t woff = (uint32_t)(wid & 3) << 21;

    // ---- prologue: issue MMA1(0) ----
    if (has_work && wid == 0 && elect_one()) {
        TC_FENCE_AFTER();
        issue_mma1(TD1, dA_src, dA_dst, dW1, dW1h, sb + TO_MBA, sb + TO_MBB);
    }

    uint32_t ph = 0;

    if (lowg) {
        // ================= warps 0-3: epi h1, issue, out-epi =================
        for (int tile = blockIdx.x; tile < ntiles; tile += gridDim.x) {
            MBAR_WAIT(sb + TO_MBB, ph);
            TC_FENCE_AFTER();
            #pragma unroll
            for (int pr = 0; pr < 2; pr++) {
                int c0 = 128 + pr * 64;
                uint32_t ra[32], rb[32];
                TC_LD_X32(ra, TD1 + c0);
                TC_LD_X32(rb, TD1 + c0 + 32);
                TC_WAIT_LD();
                uint32_t pa[16], pb[16];
                #pragma unroll
                for (int j = 0; j < 16; j++) {
                    float f0 = fmaxf(__uint_as_float(ra[2 * j])     + b1s[c0 + 2 * j],     0.0f);
                    float f1 = fmaxf(__uint_as_float(ra[2 * j + 1]) + b1s[c0 + 2 * j + 1], 0.0f);
                    __half2 hv = __floats2half2_rn(f0, f1);
                    pa[j] = *reinterpret_cast<uint32_t*>(&hv);
                    float g0 = fmaxf(__uint_as_float(rb[2 * j])     + b1s[c0 + 32 + 2 * j],     0.0f);
                    float g1 = fmaxf(__uint_as_float(rb[2 * j + 1]) + b1s[c0 + 32 + 2 * j + 1], 0.0f);
                    __half2 gv = __floats2half2_rn(g0, g1);
                    pb[j] = *reinterpret_cast<uint32_t*>(&gv);
                }
                TC_ST_X16(TH + (c0 >> 1) + woff, pa);
                TC_ST_X16(TH + ((c0 + 32) >> 1) + woff, pb);
            }
            TC_WAIT_ST();
            TC_FENCE_BEFORE();
            BAR_SYNC(0, 256);   // h complete, D1 drained, A(t+1) staged by warps 4-7

            if (wid == 0) {
                TC_FENCE_AFTER();
                if (elect_one()) {
                    // G2 FIRST in queue (TH hazard: epi(t+1) gated by MBA = after G1h0,
                    // which executes after G2 in-order)
                    #pragma unroll
                    for (int s = 0; s < 16; s++)
                        mma_f16_ts(TD2, TH + s * 8, dW2 + ((s >> 2) * 512 + (s & 3) * 2), IDESC2, s > 0);
                    TC_COMMIT(sb + TO_MBC);
                    if (tile + gridDim.x < ntiles)
                        issue_mma1(TD1, dA_src, dA_dst, dW1, dW1h, sb + TO_MBA, sb + TO_MBB);
                }
            }

            // ---- out-epi: D2 + b2 -> gmem ----
            int e = tile * 128 + gtid;
            MBAR_WAIT(sb + TO_MBC, ph);
            TC_FENCE_AFTER();
            uint32_t r0[32], r1[32];
            TC_LD_X32(r0, TD2);
            TC_LD_X32(r1, TD2 + 32);
            TC_WAIT_LD();          // drained before this warp's next BAR_SYNC -> G2(t+1) safe
            if (e < E) {
                float4* orow = reinterpret_cast<float4*>(out + (size_t)e * OUT_DIM);
                #pragma unroll
                for (int q = 0; q < 8; q++) {
                    float4 v;
                    v.x = __uint_as_float(r0[4 * q])     + b2s[4 * q];
                    v.y = __uint_as_float(r0[4 * q + 1]) + b2s[4 * q + 1];
                    v.z = __uint_as_float(r0[4 * q + 2]) + b2s[4 * q + 2];
                    v.w = __uint_as_float(r0[4 * q + 3]) + b2s[4 * q + 3];
                    orow[q] = v;
                }
                #pragma unroll
                for (int q = 0; q < 8; q++) {
                    float4 v;
                    v.x = __uint_as_float(r1[4 * q])     + b2s[32 + 4 * q];
                    v.y = __uint_as_float(r1[4 * q + 1]) + b2s[32 + 4 * q + 1];
                    v.z = __uint_as_float(r1[4 * q + 2]) + b2s[32 + 4 * q + 2];
                    v.w = __uint_as_float(r1[4 * q + 3]) + b2s[32 + 4 * q + 3];
                    orow[8 + q] = v;
                }
            }
            ph ^= 1;
        }
    } else {
        // ================= warps 4-7: epi h0 + gather =================
        const int g = gtid >> 4, sub = gtid & 15;
        for (int tile = blockIdx.x; tile < ntiles; tile += gridDim.x) {
            int ntile = tile + gridDim.x;
            bool gnext = (ntile < ntiles);
            int nbase = ntile * 128;

            // prefetch edge indices for t+1 (no A dependency; covers idx latency)
            int sidx[16], didx[16];
            if (gnext) {
                #pragma unroll
                for (int p = 0; p < 16; p++) {
                    int ne = nbase + p * 8 + g;
                    sidx[p] = (ne < E) ? edge_index[ne] : 0;
                    didx[p] = (ne < E) ? edge_index[E + ne] : 0;
                }
            }

            // ---- epi half0 (cols 0-127), gated by MBA (fires 1024 cyc before MBB) ----
            MBAR_WAIT(sb + TO_MBA, ph);
            TC_FENCE_AFTER();
            #pragma unroll
            for (int pr = 0; pr < 2; pr++) {
                int c0 = pr * 64;
                uint32_t ra[32], rb[32];
                TC_LD_X32(ra, TD1 + c0);
                TC_LD_X32(rb, TD1 + c0 + 32);
                TC_WAIT_LD();
                uint32_t pa[16], pb[16];
                #pragma unroll
                for (int j = 0; j < 16; j++) {
                    float f0 = fmaxf(__uint_as_float(ra[2 * j])     + b1s[c0 + 2 * j],     0.0f);
                    float f1 = fmaxf(__uint_as_float(ra[2 * j + 1]) + b1s[c0 + 2 * j + 1], 0.0f);
                    __half2 hv = __floats2half2_rn(f0, f1);
                    pa[j] = *reinterpret_cast<uint32_t*>(&hv);
                    float g0 = fmaxf(__uint_as_float(rb[2 * j])     + b1s[c0 + 32 + 2 * j],     0.0f);
                    float g1 = fmaxf(__uint_as_float(rb[2 * j + 1]) + b1s[c0 + 32 + 2 * j + 1], 0.0f);
                    __half2 gv = __floats2half2_rn(g0, g1);
                    pb[j] = *reinterpret_cast<uint32_t*>(&gv);
                }
                TC_ST_X16(TH + (c0 >> 1) + woff, pa);
                TC_ST_X16(TH + ((c0 + 32) >> 1) + woff, pb);
            }
            TC_WAIT_ST();
            TC_FENCE_BEFORE();

            // ---- gather A(t+1): after MBB (A free); LDG latency hidden by epi above ----
            MBAR_WAIT(sb + TO_MBB, ph);
            if (gnext) {
                uint4 reg[16];
                #pragma unroll
                for (int p = 0; p < 16; p++)
                    reg[p] = *reinterpret_cast<const uint4*>(g_xh + (size_t)sidx[p] * IN_DIM + sub * 8);
                #pragma unroll
                for (int p = 0; p < 16; p++)
                    *reinterpret_cast<uint4*>(smem + TO_SRC + kmaj_off(p * 8 + g, sub * 8, 16)) = reg[p];
                #pragma unroll
                for (int p = 0; p < 16; p++)
                    reg[p] = *reinterpret_cast<const uint4*>(g_xh + (size_t)didx[p] * IN_DIM + sub * 8);
                #pragma unroll
                for (int p = 0; p < 16; p++)
                    *reinterpret_cast<uint4*>(smem + TO_DST + kmaj_off(p * 8 + g, sub * 8, 16)) = reg[p];
                FENCE_PROXY_ASYNC();
            }
            BAR_SYNC(0, 256);   // joins warps 0-3's bar; A(t+1) visible to warp0's MMA issue
            ph ^= 1;
        }
    }

    __syncthreads();
    if (tid == 0) {
        MBAR_INVAL(sb + TO_MBA); MBAR_INVAL(sb + TO_MBB); MBAR_INVAL(sb + TO_MBC);
    }
    __syncthreads();
    if (wid == 0) TC_DEALLOC(tmem, 512);
#endif
}

// ---------------- launch ----------------
extern "C" void kernel_launch(void* const* d_in, const int* in_sizes, int n_in,
                              void* d_out, int out_size) {
    const float* x  = (const float*)d_in[0];
    const int* ei   = (const int*)d_in[1];
    const float* W1 = (const float*)d_in[2];
    const float* b1 = (const float*)d_in[3];
    const float* W2 = (const float*)d_in[4];
    const float* b2 = (const float*)d_in[5];
    float* out = (float*)d_out;

    int x_elems = in_sizes[0];
    int E = in_sizes[1] / 2;

    // Fused prep: x-conversion blocks (8 floats/thread) + weight-image blocks.
    int ngroups = (x_elems + 7) / 8;
    int nx_blocks = (ngroups + 255) / 256;
    int wtot = HIDDEN * 2 * IN_DIM + OUT_DIM * HIDDEN;   // 81920
    int nw_blocks = (wtot + 255) / 256;                  // 320
    prep_all_kernel<<<nx_blocks + nw_blocks, 256>>>(x, x_elems, nx_blocks, W1, W2);

    int dev = 0, nsm = 148;
    cudaGetDevice(&dev);
    cudaDeviceGetAttribute(&nsm, cudaDevAttrMultiProcessorCount, dev);

    // Launch only the kernel whose body survived compilation (the other is a
    // near-empty stub with few registers). Decided at capture time: deterministic.
    cudaFuncAttributes attr{};
    cudaFuncGetAttributes(&attr, edgeffn_tc);
    if (attr.numRegs > 64) {
        cudaFuncSetAttribute(edgeffn_tc, cudaFuncAttributeMaxDynamicSharedMemorySize, TC_SMEM);
        edgeffn_tc<<<nsm, 256, TC_SMEM>>>(ei, b1, b2, out, E);
    } else {
        cudaFuncSetAttribute(edgeffn_hmma, cudaFuncAttributeMaxDynamicSharedMemorySize, HMMA_SMEM);
        edgeffn_hmma<<<nsm, 256, HMMA_SMEM>>>(ei, b1, b2, out, E);
    }
}